// round 9
// baseline (speedup 1.0000x reference)
#include <cuda_runtime.h>

// CentDif: 6th-order central difference + 2-channel advection combine.
// u: [16384, 2, 2048] fp32. Persistent grid-stride kernel: 912 CTAs
// (~6/SM), each walks m-rows sequentially (regs stay low — no cross-row
// batching). Per row: thread t computes outputs [8t+4, 8t+12) from a
// 32B-aligned 16-float window per channel loaded as 2x 256-bit ld.global.nc;
// lane 255 zero-fills the 4-float ghost ends. No smem, no barriers.

#define M_DIM 16384
#define L_DIM 2048
#define IGST  10
#define NTHREADS 256
#define NCTAS 912          // 152 SMs * 6 resident CTAs

__device__ __forceinline__ void ldg256(const float* __restrict__ p, float* r) {
    asm volatile(
        "ld.global.nc.v8.f32 {%0,%1,%2,%3,%4,%5,%6,%7}, [%8];"
        : "=f"(r[0]), "=f"(r[1]), "=f"(r[2]), "=f"(r[3]),
          "=f"(r[4]), "=f"(r[5]), "=f"(r[6]), "=f"(r[7])
        : "l"(p));
}

__global__ __launch_bounds__(NTHREADS) void centdif_kernel(
    const float* __restrict__ u, float* __restrict__ out)
{
    const int t = threadIdx.x;
    const float c = (float)(1.0 / (60.0 * 0.012));  // 1/(60*DX)
    const int l0 = 8 * t + 4;

    #pragma unroll 1
    for (int m = blockIdx.x; m < M_DIM; m += NCTAS) {
        const size_t base = (size_t)m * (2 * L_DIM);

        if (t == NTHREADS - 1) {
            // Ghost ends: l in [0,4) and [2044,2048), both channels -> exactly 0.
            const float4 z = make_float4(0.f, 0.f, 0.f, 0.f);
            __stcs((float4*)(out + base), z);
            __stcs((float4*)(out + base + L_DIM - 4), z);
            __stcs((float4*)(out + base + L_DIM), z);
            __stcs((float4*)(out + base + 2 * L_DIM - 4), z);
            continue;
        }

        // Window: a[k] = u0[8t + k], b[k] = u1[8t + k], k = 0..15
        // (byte offset 32t -> 32B-aligned 256-bit loads).
        float a[16], b[16];
        const float* w0 = u + base + 8 * t;
        const float* w1 = u + base + L_DIM + 8 * t;
        ldg256(w0,     a);
        ldg256(w0 + 8, a + 8);
        ldg256(w1,     b);
        ldg256(w1 + 8, b + 8);

        // Outputs l = 8t + 4 + i, i = 0..7.
        // Taps: l-3 -> a[i+1] ... l+3 -> a[i+7]; u[l] -> a[i+4].
        float r0[8], r1[8];
        #pragma unroll
        for (int i = 0; i < 8; ++i) {
            const int l = l0 + i;
            float du0 = 0.0f, du1 = 0.0f;
            if (l >= IGST && l < L_DIM - IGST) {
                du0 = (-a[i+1] + 9.0f*a[i+2] - 45.0f*a[i+3]
                       + 45.0f*a[i+5] - 9.0f*a[i+6] + a[i+7]) * c;
                du1 = (-b[i+1] + 9.0f*b[i+2] - 45.0f*b[i+3]
                       + 45.0f*b[i+5] - 9.0f*b[i+6] + b[i+7]) * c;
            }
            const float uu0 = a[i+4];
            const float uu1 = b[i+4];
            r0[i] = -(uu1 * du0 + uu0 * du1);
            r1[i] = -(2.0f * du0 + uu1 * du1);
        }

        float4* o0 = (float4*)(out + base + l0);
        float4* o1 = (float4*)(out + base + L_DIM + l0);
        __stcs(o0 + 0, make_float4(r0[0], r0[1], r0[2], r0[3]));
        __stcs(o0 + 1, make_float4(r0[4], r0[5], r0[6], r0[7]));
        __stcs(o1 + 0, make_float4(r1[0], r1[1], r1[2], r1[3]));
        __stcs(o1 + 1, make_float4(r1[4], r1[5], r1[6], r1[7]));
    }
}

extern "C" void kernel_launch(void* const* d_in, const int* in_sizes, int n_in,
                              void* d_out, int out_size)
{
    const float* u = (const float*)d_in[0];
    float* out = (float*)d_out;
    centdif_kernel<<<NCTAS, NTHREADS>>>(u, out);
}

// round 10
// speedup vs baseline: 1.2481x; 1.2481x over previous
#include <cuda_runtime.h>

// CentDif: 6th-order central difference + 2-channel advection combine.
// u: [16384, 2, 2048] fp32. No smem/barriers. 128-thread CTAs, two per row.
// Thread t (window start w = half*1024 + 8t, 32B-aligned) computes outputs
// [w+4, w+12) from a 16-float window per channel loaded as 2x 256-bit
// ld.global.nc. Half-1 lane 127 zero-fills the 4-float ghost ends instead
// (its nominal span [2044,2052) is ghost/OOB).

#define M_DIM 16384
#define L_DIM 2048
#define IGST  10
#define NTHREADS 128

__device__ __forceinline__ void ldg256(const float* __restrict__ p, float* r) {
    asm volatile(
        "ld.global.nc.v8.f32 {%0,%1,%2,%3,%4,%5,%6,%7}, [%8];"
        : "=f"(r[0]), "=f"(r[1]), "=f"(r[2]), "=f"(r[3]),
          "=f"(r[4]), "=f"(r[5]), "=f"(r[6]), "=f"(r[7])
        : "l"(p));
}

__global__ __launch_bounds__(NTHREADS) void centdif_kernel(
    const float* __restrict__ u, float* __restrict__ out)
{
    const int bid  = blockIdx.x;
    const int m    = bid >> 1;
    const int half = bid & 1;
    const size_t base = (size_t)m * (2 * L_DIM);
    const int t = threadIdx.x;

    if (half == 1 && t == NTHREADS - 1) {
        // Ghost ends: l in [0,4) and [2044,2048), both channels -> exactly 0.
        const float4 z = make_float4(0.f, 0.f, 0.f, 0.f);
        __stcs((float4*)(out + base), z);
        __stcs((float4*)(out + base + L_DIM - 4), z);
        __stcs((float4*)(out + base + L_DIM), z);
        __stcs((float4*)(out + base + 2 * L_DIM - 4), z);
        return;
    }

    const float c = (float)(1.0 / (60.0 * 0.012));  // 1/(60*DX)
    const int w  = half * (L_DIM / 2) + 8 * t;      // window start (mult of 8 -> 32B aligned)
    const int l0 = w + 4;                           // first output

    // Window: a[k] = u0[w + k], b[k] = u1[w + k], k = 0..15.
    float a[16], b[16];
    const float* w0 = u + base + w;
    const float* w1 = u + base + L_DIM + w;
    ldg256(w0,     a);
    ldg256(w0 + 8, a + 8);
    ldg256(w1,     b);
    ldg256(w1 + 8, b + 8);

    // Outputs l = l0 + i, i = 0..7.
    // Taps: l-3 -> a[i+1] ... l+3 -> a[i+7]; u[l] -> a[i+4].
    float r0[8], r1[8];
    #pragma unroll
    for (int i = 0; i < 8; ++i) {
        const int l = l0 + i;
        float du0 = 0.0f, du1 = 0.0f;
        if (l >= IGST && l < L_DIM - IGST) {
            du0 = (-a[i+1] + 9.0f*a[i+2] - 45.0f*a[i+3]
                   + 45.0f*a[i+5] - 9.0f*a[i+6] + a[i+7]) * c;
            du1 = (-b[i+1] + 9.0f*b[i+2] - 45.0f*b[i+3]
                   + 45.0f*b[i+5] - 9.0f*b[i+6] + b[i+7]) * c;
        }
        const float uu0 = a[i+4];
        const float uu1 = b[i+4];
        r0[i] = -(uu1 * du0 + uu0 * du1);
        r1[i] = -(2.0f * du0 + uu1 * du1);
    }

    float4* o0 = (float4*)(out + base + l0);
    float4* o1 = (float4*)(out + base + L_DIM + l0);
    __stcs(o0 + 0, make_float4(r0[0], r0[1], r0[2], r0[3]));
    __stcs(o0 + 1, make_float4(r0[4], r0[5], r0[6], r0[7]));
    __stcs(o1 + 0, make_float4(r1[0], r1[1], r1[2], r1[3]));
    __stcs(o1 + 1, make_float4(r1[4], r1[5], r1[6], r1[7]));
}

extern "C" void kernel_launch(void* const* d_in, const int* in_sizes, int n_in,
                              void* d_out, int out_size)
{
    const float* u = (const float*)d_in[0];
    float* out = (float*)d_out;
    centdif_kernel<<<M_DIM * 2, NTHREADS>>>(u, out);
}

// round 11
// speedup vs baseline: 1.2539x; 1.0047x over previous
#include <cuda_runtime.h>

// CentDif: 6th-order central difference + 2-channel advection combine.
// u: [16384, 2, 2048] fp32. Converged streaming shape: no smem/barriers,
// 128-thread CTAs (two per m-row), 256-bit loads AND 256-bit streaming
// stores (1KB dense bursts per warp instruction on both directions).
// Thread t (window start w = half*1024 + 8t, 32B-aligned) computes outputs
// [w+4, w+12); half-1 lane 127 zero-fills the 4-float ghost ends instead.

#define M_DIM 16384
#define L_DIM 2048
#define IGST  10
#define NTHREADS 128

__device__ __forceinline__ void ldg256(const float* __restrict__ p, float* r) {
    asm volatile(
        "ld.global.nc.v8.f32 {%0,%1,%2,%3,%4,%5,%6,%7}, [%8];"
        : "=f"(r[0]), "=f"(r[1]), "=f"(r[2]), "=f"(r[3]),
          "=f"(r[4]), "=f"(r[5]), "=f"(r[6]), "=f"(r[7])
        : "l"(p));
}

__device__ __forceinline__ void stg256_cs(float* __restrict__ p, const float* r) {
    asm volatile(
        "st.global.cs.v8.f32 [%0], {%1,%2,%3,%4,%5,%6,%7,%8};"
        :: "l"(p),
           "f"(r[0]), "f"(r[1]), "f"(r[2]), "f"(r[3]),
           "f"(r[4]), "f"(r[5]), "f"(r[6]), "f"(r[7])
        : "memory");
}

__global__ __launch_bounds__(NTHREADS) void centdif_kernel(
    const float* __restrict__ u, float* __restrict__ out)
{
    const int bid  = blockIdx.x;
    const int m    = bid >> 1;
    const int half = bid & 1;
    const size_t base = (size_t)m * (2 * L_DIM);
    const int t = threadIdx.x;

    if (half == 1 && t == NTHREADS - 1) {
        // Ghost ends: l in [0,4) and [2044,2048), both channels -> exactly 0.
        const float4 z = make_float4(0.f, 0.f, 0.f, 0.f);
        __stcs((float4*)(out + base), z);
        __stcs((float4*)(out + base + L_DIM - 4), z);
        __stcs((float4*)(out + base + L_DIM), z);
        __stcs((float4*)(out + base + 2 * L_DIM - 4), z);
        return;
    }

    const float c = (float)(1.0 / (60.0 * 0.012));  // 1/(60*DX)
    const int w  = half * (L_DIM / 2) + 8 * t;      // window start (32B-aligned)
    const int l0 = w + 4;                           // first output (16B-aligned... w+4 mult of 4)

    // Window: a[k] = u0[w + k], b[k] = u1[w + k], k = 0..15.
    float a[16], b[16];
    const float* w0 = u + base + w;
    const float* w1 = u + base + L_DIM + w;
    ldg256(w0,     a);
    ldg256(w0 + 8, a + 8);
    ldg256(w1,     b);
    ldg256(w1 + 8, b + 8);

    // Outputs l = l0 + i, i = 0..7.
    // Taps: l-3 -> a[i+1] ... l+3 -> a[i+7]; u[l] -> a[i+4].
    float r0[8], r1[8];
    #pragma unroll
    for (int i = 0; i < 8; ++i) {
        const int l = l0 + i;
        float du0 = 0.0f, du1 = 0.0f;
        if (l >= IGST && l < L_DIM - IGST) {
            du0 = (-a[i+1] + 9.0f*a[i+2] - 45.0f*a[i+3]
                   + 45.0f*a[i+5] - 9.0f*a[i+6] + a[i+7]) * c;
            du1 = (-b[i+1] + 9.0f*b[i+2] - 45.0f*b[i+3]
                   + 45.0f*b[i+5] - 9.0f*b[i+6] + b[i+7]) * c;
        }
        const float uu0 = a[i+4];
        const float uu1 = b[i+4];
        r0[i] = -(uu1 * du0 + uu0 * du1);
        r1[i] = -(2.0f * du0 + uu1 * du1);
    }

    // 256-bit streaming stores. out+base+l0 has offset 4*l0 bytes, l0 = w+4,
    // w mult of 8 -> 4*l0 = 32w'+16: only 16B-aligned. v8 needs 32B alignment,
    // so store the two channels' 8-float runs from their 32B-aligned bases:
    // split as [l0-? ] — instead store at l0 via two halves when misaligned.
    // l0 % 8 == 4 always, so use one 16B store + one 32B-aligned v8? Simpler:
    // keep correctness — do aligned v8 only when (l0 & 7) == 0, else 2x float4.
    if ((l0 & 7) == 0) {
        stg256_cs(out + base + l0, r0);
        stg256_cs(out + base + L_DIM + l0, r1);
    } else {
        float4* o0 = (float4*)(out + base + l0);
        float4* o1 = (float4*)(out + base + L_DIM + l0);
        __stcs(o0 + 0, make_float4(r0[0], r0[1], r0[2], r0[3]));
        __stcs(o0 + 1, make_float4(r0[4], r0[5], r0[6], r0[7]));
        __stcs(o1 + 0, make_float4(r1[0], r1[1], r1[2], r1[3]));
        __stcs(o1 + 1, make_float4(r1[4], r1[5], r1[6], r1[7]));
    }
}

extern "C" void kernel_launch(void* const* d_in, const int* in_sizes, int n_in,
                              void* d_out, int out_size)
{
    const float* u = (const float*)d_in[0];
    float* out = (float*)d_out;
    centdif_kernel<<<M_DIM * 2, NTHREADS>>>(u, out);
}